// round 12
// baseline (speedup 1.0000x reference)
#include <cuda_runtime.h>
#include <math.h>

#define CC 31
#define HO 256
#define WO 256
#define NPIX (HO*WO)          // 65536
#define HI 128
#define WI 128

typedef unsigned long long ull;

__device__ __forceinline__ ull pk2(float lo, float hi) {
    ull r; asm("mov.b64 %0,{%1,%2};" : "=l"(r) : "f"(lo), "f"(hi)); return r;
}
__device__ __forceinline__ void fma2(ull& d, ull a, ull b) {
    asm("fma.rn.f32x2 %0,%1,%2,%0;" : "+l"(d) : "l"(a), "l"(b));
}
__device__ __forceinline__ float2 upk(ull v) {
    float2 r; asm("mov.b64 {%0,%1},%2;" : "=f"(r.x), "=f"(r.y) : "l"(v)); return r;
}

// ---------------- static device scratch ----------------
__device__ float d_gcls[5*3*3*225]; // 45 boundary-class composed 9x5x5 kernels
__device__ float d_offp[8];         // per-parity offsets (p = (i&1)*2 | (j&1))
__device__ float d_Mp[4*961];       // per-parity 31x31 mixing matrices

// ============================ k0: all precompute, 49 blocks, redundant ============================
__global__ __launch_bounds__(256) void k0(
    const float* __restrict__ WE,  // (4,32,1,5,3,3) = 4*1440
    const float* __restrict__ WC,
    const float* __restrict__ W2,  // (4,31,31)
    const float* __restrict__ bw1, const float* __restrict__ bb1,
    const float* __restrict__ bw2, const float* __restrict__ bb2,
    const float* __restrict__ r2w, const float* __restrict__ r2b,
    const float* __restrict__ ow,  const float* __restrict__ ob,
    const float* __restrict__ l1w, const float* __restrict__ l1b,
    const float* __restrict__ l2w, const float* __restrict__ l2b)
{
    __shared__ float s_bw2[4096];
    __shared__ float wem[1440], wcm[1440], G2s[2025];
    __shared__ float s_bw1[192], s_bb1[64], s_bb2[64];
    __shared__ float s_r2w[256], s_r2b[4], s_ow[128], s_ob[2];
    __shared__ float s_l1w[128], s_l1b[64], s_l2w[256], s_l2b[4];
    __shared__ float e1s[4][64], e2s[4][64];
    __shared__ float h1s[2][64], lgs[2][4];
    __shared__ float r2s[4][4], rsum_s[4], offs_s[8];

    int tid = threadIdx.x;
    int bid = blockIdx.x;

    for (int t = tid; t < 4096; t += 256) s_bw2[t] = bw2[t];
    for (int t = tid; t < 192;  t += 256) s_bw1[t] = bw1[t];
    for (int t = tid; t < 64;   t += 256) { s_bb1[t] = bb1[t]; s_bb2[t] = bb2[t];
                                            s_l1b[t] = l1b[t]; }
    for (int t = tid; t < 256;  t += 256) { s_r2w[t] = r2w[t]; s_l2w[t] = l2w[t]; }
    for (int t = tid; t < 128;  t += 256) { s_ow[t] = ow[t]; s_l1w[t] = l1w[t]; }
    if (tid < 4) { s_r2b[tid] = r2b[tid]; s_l2b[tid] = l2b[tid]; }
    if (tid < 2) s_ob[tid] = ob[tid];
    __syncthreads();

    {
        int p = tid >> 6, o = tid & 63;
        float ch = (p & 2) ? 0.25f : -0.25f;
        float cw = (p & 1) ? 0.25f : -0.25f;
        float a = s_bw1[o*3+0]*0.5f + s_bw1[o*3+1]*ch + s_bw1[o*3+2]*cw + s_bb1[o];
        e1s[p][o] = a > 0.f ? a : 0.f;
    }
    if (tid < 128) {
        int r = tid >> 6, o = tid & 63;
        float chr = r ? 0.25f : -0.25f;
        float a = s_l1w[o*2+0]*0.5f + s_l1w[o*2+1]*chr + s_l1b[o];
        h1s[r][o] = a > 0.f ? a : 0.f;
    }
    __syncthreads();

    {
        int p = tid >> 6, o = tid & 63;
        float a = s_bb2[o];
        #pragma unroll 8
        for (int i = 0; i < 64; i++) a += s_bw2[o*64+i]*e1s[p][i];
        e2s[p][o] = a > 0.f ? a : 0.f;
    }
    if (tid < 8) {
        int r = tid >> 2, e = tid & 3;
        float a = s_l2b[e];
        #pragma unroll 8
        for (int o = 0; o < 64; o++) a += s_l2w[e*64+o]*h1s[r][o];
        lgs[r][e] = a;
    }
    __syncthreads();

    if (tid < 24) {
        int p = tid / 6, u = tid % 6;
        if (u < 2) {
            float a = s_ob[u];
            for (int i = 0; i < 64; i++) a += s_ow[u*64+i]*e2s[p][i];
            offs_s[p*2+u] = a;
        } else {
            int e = u - 2;
            float a = s_r2b[e];
            for (int i = 0; i < 64; i++) a += s_r2w[e*64+i]*e2s[p][i];
            r2s[p][e] = 1.f/(1.f+expf(-a));
        }
    }
    if (tid >= 32 && tid < 36) {
        int e = tid - 32;
        float rsv = 0.f;
        #pragma unroll
        for (int r = 0; r < 2; r++) {
            float m = fmaxf(fmaxf(lgs[r][0], lgs[r][1]), fmaxf(lgs[r][2], lgs[r][3]));
            float s = 0.f;
            #pragma unroll
            for (int j = 0; j < 4; j++) s += expf(lgs[r][j]-m);
            rsv += expf(lgs[r][e]-m)/s;
        }
        rsum_s[e] = rsv;
    }
    __syncthreads();

    if (bid < 45) {
        float r0 = rsum_s[0], r1 = rsum_s[1], r2 = rsum_s[2], r3 = rsum_s[3];
        for (int idx = tid; idx < 32*45; idx += 256) {
            wem[idx] = r0*WE[idx] + r1*WE[1440+idx] + r2*WE[2880+idx] + r3*WE[4320+idx];
            wcm[idx] = r0*WC[idx] + r1*WC[1440+idx] + r2*WC[2880+idx] + r3*WC[4320+idx];
        }
        __syncthreads();

        for (int idx = tid; idx < 45*45; idx += 256) {
            int q = idx / 45, r = idx % 45;
            float a0 = 0.f, a1 = 0.f;
            #pragma unroll
            for (int k = 0; k < 32; k += 2) {
                a0 += wcm[k*45+q]*wem[k*45+r];
                a1 += wcm[(k+1)*45+q]*wem[(k+1)*45+r];
            }
            G2s[idx] = a0 + a1;
        }
        __syncthreads();

        if (tid < 225) {
            const int qzl_t[5] = {2,1,0,0,0}, qzh_t[5] = {4,4,4,3,2};
            const int q3l_t[3] = {0,1,0},     q3h_t[3] = {2,2,1};
            int cls = bid;
            int zc = cls / 9, yc = (cls % 9) / 3, xc = cls % 3;
            int s = tid;
            int sz = s / 25, sy = (s % 25) / 5, sx = s % 5;
            int qzl = max(qzl_t[zc], sz-4), qzh = min(qzh_t[zc], sz);
            int qyl = max(q3l_t[yc], sy-2), qyh = min(q3h_t[yc], sy);
            int qxl = max(q3l_t[xc], sx-2), qxh = min(q3h_t[xc], sx);
            float acc = 0.f;
            for (int qz = qzl; qz <= qzh; qz++) {
                const float* Gz = G2s + qz*9*45 + (sz-qz)*9;
                for (int qy = qyl; qy <= qyh; qy++) {
                    const float* Gy = Gz + qy*3*45 + (sy-qy)*3;
                    for (int qx = qxl; qx <= qxh; qx++)
                        acc += Gy[qx*45 + (sx-qx)];
                }
            }
            d_gcls[cls*225 + s] = acc;
        }
    } else {
        int p = bid - 45;
        float r0 = r2s[p][0], r1 = r2s[p][1], r2 = r2s[p][2], r3 = r2s[p][3];
        for (int ij = tid; ij < 961; ij += 256)
            d_Mp[p*961 + ij] = r0*W2[ij] + r1*W2[961+ij] + r2*W2[2*961+ij] + r3*W2[3*961+ij];
        if (p == 0 && tid < 8) d_offp[tid] = offs_s[tid];
    }
}

// ============================ fused: bilinear + packed conv (prepacked weights) + mix ============================
// depth-contiguous tile: tile[(yy*36+xx)*36 + d], pad stride 36 (16B-aligned columns).
#define NT    432             // 12*36 taps
#define DSTR  36
#define TILE_F (NT*DSTR)      // 15552
#define WPK_F  (4*25*52)      // 5200: 4 slots x 25 taps x 26 packed ull (52 floats)
#define MROW   32
#define MPS_F  (4*31*MROW)    // 3968
#define SMEM_F (TILE_F + WPK_F + MPS_F + 8)

// VE(j): packed depth pair (2(j-2), 2(j-2)+1) from the vq[] ull2 registers.
#define VE(j) ((((j) & 1) == 0) ? vq[((j)-2) >> 1].x : vq[((j)-2) >> 1].y)

__global__ __launch_bounds__(256, 2) void kfused(const float* __restrict__ x,
                                                 float* __restrict__ out)
{
    extern __shared__ float sm[];
    float* tile = sm;
    float* wpk  = sm + TILE_F;
    float* Mps  = sm + TILE_F + WPK_F;
    float* offs = Mps + MPS_F;

    int tx = threadIdx.x, ty = threadIdx.y;
    int tid = ty*32 + tx;
    int gx0 = blockIdx.x*32 - 2, gy0 = blockIdx.y*8 - 2;

    if (tid < 8) offs[tid] = d_offp[tid];
    int oylo = blockIdx.y*8, oxlo = blockIdx.x*32;
    int yec = (oylo == 0) ? 1 : ((oylo + 7 >= HO-1) ? 2 : 0);
    int xec = (oxlo == 0) ? 1 : ((oxlo + 31 >= WO-1) ? 2 : 0);

    // ---- build packed weight table: wpk[slot][tap][26 ull] ----
    for (int e = tid; e < 4*25*26; e += 256) {
        int slot = e / 650, r = e % 650;
        int tap = r / 26, w = r % 26;
        int ys = (slot & 1) ? yec : 0;
        int xs = (slot & 2) ? xec : 0;
        int cb = (ys*3 + xs)*225 + tap;
        const float* g0 = d_gcls + cb;             // zc=0
        const float* g1 = d_gcls + 1*9*225 + cb;   // zc=1
        const float* gI = d_gcls + 2*9*225 + cb;   // zc=2 (interior)
        const float* g3 = d_gcls + 3*9*225 + cb;   // zc=3
        const float* g4 = d_gcls + 4*9*225 + cb;   // zc=4
        float lo, hi;
        if (w <= 8)       { lo = hi = gI[w*25]; }                         // wII[sz]
        else if (w <= 11) { int sz = 2*(w-7);  lo = g0[sz*25]; hi = g1[sz*25]; }   // E0: sz=4,6,8
        else if (w <= 15) { int szh = w-12;                                // E14
            if (szh <= 2) { lo = gI[2*szh*25]; hi = g3[2*szh*25]; }
            else          { lo = gI[150];      hi = 0.f; } }               // sz=6
        else if (w <= 18) { int sz = 2*(w-16); lo = g4[sz*25]; hi = 0.f; } // E15: sz=0,2,4
        else if (w <= 21) { int sz = 2*(w-19)+3; lo = g1[sz*25]; hi = gI[sz*25]; } // O0: sz=3,5,7
        else if (w <= 24) { int szh = w-22;                                // O14
            if (szh <= 1) { int sz = 2*szh+1; lo = g3[sz*25]; hi = g4[sz*25]; }
            else          { lo = g3[125]; hi = 0.f; } }                    // sz=5
        else              { lo = g0[125]; hi = g0[175]; }                  // d0 fixup: g0[5], g0[7]
        *(ull*)(wpk + (slot*25 + tap)*52 + 2*w) = pk2(lo, hi);
    }
    for (int t = tid; t < MPS_F; t += 256) {
        int p = t / (31*MROW), r = t % (31*MROW);
        int ii = r / MROW, jj = r % MROW;
        Mps[t] = (jj < 31) ? d_Mp[p*961 + ii*31 + jj] : 0.f;
    }
    __syncthreads();

    // ---- bilinear halo tile from x (vectorized STS.128, depth-contiguous) ----
    for (int t = tid; t < NT; t += 256) {
        int yy = t / 36, xx = t % 36;
        int gy = gy0 + yy, gx = gx0 + xx;
        float* dst = tile + t*DSTR;
        if (gy < 0 || gy >= HO || gx < 0 || gx >= WO) {
            #pragma unroll
            for (int g = 0; g < 8; g++)
                *(float4*)(dst + 4*g) = make_float4(0.f, 0.f, 0.f, 0.f);
        } else {
            int p = ((gy & 1) << 1) | (gx & 1);
            float ix = (gx + 0.5f)*0.5f - 0.5f + offs[p*2+0];
            float iy = (gy + 0.5f)*0.5f - 0.5f + offs[p*2+1];
            float x0f = floorf(ix), y0f = floorf(iy);
            float wx1 = ix - x0f, wy1 = iy - y0f;
            int x0 = (int)x0f, y0 = (int)y0f;
            float vx0 = (x0   >= 0 && x0   <= WI-1) ? 1.f : 0.f;
            float vx1 = (x0+1 >= 0 && x0+1 <= WI-1) ? 1.f : 0.f;
            float vy0 = (y0   >= 0 && y0   <= HI-1) ? 1.f : 0.f;
            float vy1 = (y0+1 >= 0 && y0+1 <= HI-1) ? 1.f : 0.f;
            int xi0 = min(max(x0,   0), WI-1), xi1 = min(max(x0+1, 0), WI-1);
            int yi0 = min(max(y0,   0), HI-1), yi1 = min(max(y0+1, 0), HI-1);
            float w00 = (1.f-wy1)*(1.f-wx1)*vy0*vx0;
            float w01 = (1.f-wy1)*wx1*vy0*vx1;
            float w10 = wy1*(1.f-wx1)*vy1*vx0;
            float w11 = wy1*wx1*vy1*vx1;
            int b00 = yi0*WI + xi0, b01 = yi0*WI + xi1;
            int b10 = yi1*WI + xi0, b11 = yi1*WI + xi1;
            #pragma unroll 2
            for (int g = 0; g < 8; g++) {
                float4 buf;
                float v0, v1, v2, v3;
                {
                    const float* xc = x + (4*g+0)*(HI*WI);
                    v0 = w00*__ldg(xc+b00) + w01*__ldg(xc+b01)
                       + w10*__ldg(xc+b10) + w11*__ldg(xc+b11);
                }
                {
                    const float* xc = x + (4*g+1)*(HI*WI);
                    v1 = w00*__ldg(xc+b00) + w01*__ldg(xc+b01)
                       + w10*__ldg(xc+b10) + w11*__ldg(xc+b11);
                }
                {
                    const float* xc = x + (4*g+2)*(HI*WI);
                    v2 = w00*__ldg(xc+b00) + w01*__ldg(xc+b01)
                       + w10*__ldg(xc+b10) + w11*__ldg(xc+b11);
                }
                if (g < 7) {
                    const float* xc = x + (4*g+3)*(HI*WI);
                    v3 = w00*__ldg(xc+b00) + w01*__ldg(xc+b01)
                       + w10*__ldg(xc+b10) + w11*__ldg(xc+b11);
                } else {
                    v3 = 0.f;   // depth 31 pad
                }
                buf.x = v0; buf.y = v1; buf.z = v2; buf.w = v3;
                *(float4*)(dst + 4*g) = buf;
            }
        }
    }
    __syncthreads();

    int oy = blockIdx.y*8 + ty, ox = blockIdx.x*32 + tx;
    int yfl = (oy == 0 || oy == HO-1) ? 1 : 0;
    int xfl = (ox == 0 || ox == WO-1) ? 1 : 0;
    int slotIdx = yfl + 2*xfl;
    const float* ctr = tile + ((ty+2)*36 + (tx+2))*DSTR;

    // merged-pass dual-parity packed accumulators
    ull accE[16], accO[15];
    float acc0x = 0.f;
    #pragma unroll
    for (int k = 0; k < 16; k++) accE[k] = *(const ull*)(ctr + 2*k);   // residual init
    #pragma unroll
    for (int k = 0; k < 15; k++) accO[k] = 0ULL;

    #pragma unroll 1
    for (int sy = 0; sy < 5; sy++) {
        #pragma unroll 1
        for (int sx = 0; sx < 5; sx++) {
            const float* tp = tile + ((ty+sy)*36 + (tx+sx))*DSTR;
            const ull* wq = (const ull*)(wpk + (slotIdx*25 + sy*5 + sx)*52);
            ulonglong2 vq[8];
            #pragma unroll
            for (int m = 0; m < 8; m++) vq[m] = *(const ulonglong2*)(tp + 4*m);

            // ---- even sz (accE: pairs (2k,2k+1)) ----
            #pragma unroll
            for (int szh = 0; szh < 5; szh++) {
                ull wII = wq[2*szh];
                if (szh >= 2) {                        // sz>=4: pair (d0,d1)=(g0,g1)
                    fma2(accE[0], VE(szh), wq[9 + szh - 2]);
                }
                #pragma unroll
                for (int k = 1; k <= 13; k++) {
                    if (!(k == 1 && szh == 0))         // ve[1] is zero
                        fma2(accE[k], VE(k+szh), wII);
                }
                if (szh <= 2) {                        // sz<=4: (gi,g3)
                    fma2(accE[14], VE(14+szh), wq[12+szh]);
                } else if (szh == 3) {                 // sz=6: (gi,0)
                    fma2(accE[14], VE(17), wq[15]);
                }                                      // sz=8: v zero, skip
                if (szh <= 2) {                        // sz<=4: (g4,0)
                    fma2(accE[15], VE(15+szh), wq[16+szh]);
                }
            }
            // ---- odd sz (accO: pairs (2k+1,2k+2)) ----
            #pragma unroll
            for (int szh = 0; szh < 4; szh++) {
                const int h = szh + 1;
                ull wII = wq[2*szh + 1];
                if (szh >= 1) {                        // sz>=3: pair (d1,d2)=(g1,gi)
                    fma2(accO[0], VE(h), wq[19 + szh - 1]);
                }
                #pragma unroll
                for (int k = 1; k <= 13; k++)
                    fma2(accO[k], VE(k+h), wII);
                if (szh <= 1) {                        // sz=1,3: (g3,g4)
                    fma2(accO[14], VE(14+h), wq[22+szh]);
                } else if (szh == 2) {                 // sz=5: (g3,0)
                    fma2(accO[14], VE(17), wq[24]);
                }                                      // sz=7: skip
            }
            // d0 fixup (odd sz>=5): g0[5]*v[1] + g0[7]*v[3]
            {
                float2 dw = upk(wq[25]);
                acc0x += dw.x * upk(VE(2)).y;
                acc0x += dw.y * upk(VE(3)).y;
            }
        }
    }

    // combine
    float a[32];
    #pragma unroll
    for (int k = 0; k < 16; k++) { float2 e = upk(accE[k]); a[2*k] = e.x; a[2*k+1] = e.y; }
    #pragma unroll
    for (int k = 0; k < 15; k++) { float2 o = upk(accO[k]); a[2*k+1] += o.x; a[2*k+2] += o.y; }
    a[0] += acc0x;
    a[31] = 0.f;

    // per-pixel channel mix + fea0 (float4 reads of padded M rows)
    const float* M = Mps + (((oy & 1) << 1) | (ox & 1))*(31*MROW);
    int pix = oy*WO + ox;
    #pragma unroll 1
    for (int ii = 0; ii < 30; ii += 2) {
        const float* M0 = M + ii*MROW;
        const float* M1 = M0 + MROW;
        float s00 = 0.f, s01 = 0.f, s10 = 0.f, s11 = 0.f;
        #pragma unroll
        for (int jc = 0; jc < 8; jc += 2) {
            float4 a0 = *(const float4*)(M0 + jc*4);
            float4 b0 = *(const float4*)(M0 + jc*4 + 4);
            float4 a1 = *(const float4*)(M1 + jc*4);
            float4 b1 = *(const float4*)(M1 + jc*4 + 4);
            int j0 = jc*4;
            s00 += a0.x*a[j0+0] + a0.y*a[j0+1] + a0.z*a[j0+2] + a0.w*a[j0+3];
            s01 += b0.x*a[j0+4] + b0.y*a[j0+5] + b0.z*a[j0+6] + b0.w*a[j0+7];
            s10 += a1.x*a[j0+0] + a1.y*a[j0+1] + a1.z*a[j0+2] + a1.w*a[j0+3];
            s11 += b1.x*a[j0+4] + b1.y*a[j0+5] + b1.z*a[j0+6] + b1.w*a[j0+7];
        }
        out[ii*NPIX + pix]     = ctr[ii]   + (s00 + s01);
        out[(ii+1)*NPIX + pix] = ctr[ii+1] + (s10 + s11);
    }
    {
        const float* M0 = M + 30*MROW;
        float s0 = 0.f, s1 = 0.f;
        #pragma unroll
        for (int jc = 0; jc < 8; jc += 2) {
            float4 a0 = *(const float4*)(M0 + jc*4);
            float4 b0 = *(const float4*)(M0 + jc*4 + 4);
            int j0 = jc*4;
            s0 += a0.x*a[j0+0] + a0.y*a[j0+1] + a0.z*a[j0+2] + a0.w*a[j0+3];
            s1 += b0.x*a[j0+4] + b0.y*a[j0+5] + b0.z*a[j0+6] + b0.w*a[j0+7];
        }
        out[30*NPIX + pix] = ctr[30] + (s0 + s1);
    }
}

// ============================ launch ============================
extern "C" void kernel_launch(void* const* d_in, const int* in_sizes, int n_in,
                              void* d_out, int out_size)
{
    const float* x   = (const float*)d_in[0];
    // d_in[1] = scale (always 2; parity tables assume it)
    const float* WE  = (const float*)d_in[2];
    const float* WC  = (const float*)d_in[3];
    const float* W2  = (const float*)d_in[4];
    const float* bw1 = (const float*)d_in[5];
    const float* bb1 = (const float*)d_in[6];
    const float* bw2 = (const float*)d_in[7];
    const float* bb2 = (const float*)d_in[8];
    const float* r2w = (const float*)d_in[9];
    const float* r2b = (const float*)d_in[10];
    const float* ow  = (const float*)d_in[11];
    const float* ob  = (const float*)d_in[12];
    const float* l1w = (const float*)d_in[13];
    const float* l1b = (const float*)d_in[14];
    const float* l2w = (const float*)d_in[15];
    const float* l2b = (const float*)d_in[16];
    float* out = (float*)d_out;

    static int smem_set = 0;
    if (!smem_set) {
        cudaFuncSetAttribute(kfused, cudaFuncAttributeMaxDynamicSharedMemorySize,
                             SMEM_F * (int)sizeof(float));
        smem_set = 1;
    }

    k0<<<49, 256>>>(WE, WC, W2, bw1, bb1, bw2, bb2,
                    r2w, r2b, ow, ob, l1w, l1b, l2w, l2b);
    kfused<<<dim3(WO/32, HO/8), dim3(32, 8), SMEM_F*(int)sizeof(float)>>>(x, out);
}

// round 13
// speedup vs baseline: 1.0899x; 1.0899x over previous
#include <cuda_runtime.h>
#include <math.h>

#define CC 31
#define HO 256
#define WO 256
#define NPIX (HO*WO)          // 65536
#define HI 128
#define WI 128

typedef unsigned long long ull;

__device__ __forceinline__ ull pk2(float lo, float hi) {
    ull r; asm("mov.b64 %0,{%1,%2};" : "=l"(r) : "f"(lo), "f"(hi)); return r;
}
__device__ __forceinline__ void fma2(ull& d, ull a, ull b) {
    asm("fma.rn.f32x2 %0,%1,%2,%0;" : "+l"(d) : "l"(a), "l"(b));
}
__device__ __forceinline__ float2 upk(ull v) {
    float2 r; asm("mov.b64 {%0,%1},%2;" : "=f"(r.x), "=f"(r.y) : "l"(v)); return r;
}

// ---------------- static device scratch ----------------
__device__ float d_gcls[5*3*3*225]; // 45 boundary-class composed 9x5x5 kernels
__device__ float d_offp[8];         // per-parity offsets (p = (i&1)*2 | (j&1))
__device__ float d_Mp[4*961];       // per-parity 31x31 mixing matrices

// ============================ k0: all precompute, 49 blocks, redundant ============================
__global__ __launch_bounds__(256) void k0(
    const float* __restrict__ WE,
    const float* __restrict__ WC,
    const float* __restrict__ W2,
    const float* __restrict__ bw1, const float* __restrict__ bb1,
    const float* __restrict__ bw2, const float* __restrict__ bb2,
    const float* __restrict__ r2w, const float* __restrict__ r2b,
    const float* __restrict__ ow,  const float* __restrict__ ob,
    const float* __restrict__ l1w, const float* __restrict__ l1b,
    const float* __restrict__ l2w, const float* __restrict__ l2b)
{
    __shared__ float s_bw2[4096];
    __shared__ float wem[1440], wcm[1440], G2s[2025];
    __shared__ float s_bw1[192], s_bb1[64], s_bb2[64];
    __shared__ float s_r2w[256], s_r2b[4], s_ow[128], s_ob[2];
    __shared__ float s_l1w[128], s_l1b[64], s_l2w[256], s_l2b[4];
    __shared__ float e1s[4][64], e2s[4][64];
    __shared__ float h1s[2][64], lgs[2][4];
    __shared__ float r2s[4][4], rsum_s[4], offs_s[8];

    int tid = threadIdx.x;
    int bid = blockIdx.x;

    for (int t = tid; t < 4096; t += 256) s_bw2[t] = bw2[t];
    for (int t = tid; t < 192;  t += 256) s_bw1[t] = bw1[t];
    for (int t = tid; t < 64;   t += 256) { s_bb1[t] = bb1[t]; s_bb2[t] = bb2[t];
                                            s_l1b[t] = l1b[t]; }
    for (int t = tid; t < 256;  t += 256) { s_r2w[t] = r2w[t]; s_l2w[t] = l2w[t]; }
    for (int t = tid; t < 128;  t += 256) { s_ow[t] = ow[t]; s_l1w[t] = l1w[t]; }
    if (tid < 4) { s_r2b[tid] = r2b[tid]; s_l2b[tid] = l2b[tid]; }
    if (tid < 2) s_ob[tid] = ob[tid];
    __syncthreads();

    {
        int p = tid >> 6, o = tid & 63;
        float ch = (p & 2) ? 0.25f : -0.25f;
        float cw = (p & 1) ? 0.25f : -0.25f;
        float a = s_bw1[o*3+0]*0.5f + s_bw1[o*3+1]*ch + s_bw1[o*3+2]*cw + s_bb1[o];
        e1s[p][o] = a > 0.f ? a : 0.f;
    }
    if (tid < 128) {
        int r = tid >> 6, o = tid & 63;
        float chr = r ? 0.25f : -0.25f;
        float a = s_l1w[o*2+0]*0.5f + s_l1w[o*2+1]*chr + s_l1b[o];
        h1s[r][o] = a > 0.f ? a : 0.f;
    }
    __syncthreads();

    {
        int p = tid >> 6, o = tid & 63;
        float a = s_bb2[o];
        #pragma unroll 8
        for (int i = 0; i < 64; i++) a += s_bw2[o*64+i]*e1s[p][i];
        e2s[p][o] = a > 0.f ? a : 0.f;
    }
    if (tid < 8) {
        int r = tid >> 2, e = tid & 3;
        float a = s_l2b[e];
        #pragma unroll 8
        for (int o = 0; o < 64; o++) a += s_l2w[e*64+o]*h1s[r][o];
        lgs[r][e] = a;
    }
    __syncthreads();

    if (tid < 24) {
        int p = tid / 6, u = tid % 6;
        if (u < 2) {
            float a = s_ob[u];
            for (int i = 0; i < 64; i++) a += s_ow[u*64+i]*e2s[p][i];
            offs_s[p*2+u] = a;
        } else {
            int e = u - 2;
            float a = s_r2b[e];
            for (int i = 0; i < 64; i++) a += s_r2w[e*64+i]*e2s[p][i];
            r2s[p][e] = 1.f/(1.f+expf(-a));
        }
    }
    if (tid >= 32 && tid < 36) {
        int e = tid - 32;
        float rsv = 0.f;
        #pragma unroll
        for (int r = 0; r < 2; r++) {
            float m = fmaxf(fmaxf(lgs[r][0], lgs[r][1]), fmaxf(lgs[r][2], lgs[r][3]));
            float s = 0.f;
            #pragma unroll
            for (int j = 0; j < 4; j++) s += expf(lgs[r][j]-m);
            rsv += expf(lgs[r][e]-m)/s;
        }
        rsum_s[e] = rsv;
    }
    __syncthreads();

    if (bid < 45) {
        float r0 = rsum_s[0], r1 = rsum_s[1], r2 = rsum_s[2], r3 = rsum_s[3];
        for (int idx = tid; idx < 32*45; idx += 256) {
            wem[idx] = r0*WE[idx] + r1*WE[1440+idx] + r2*WE[2880+idx] + r3*WE[4320+idx];
            wcm[idx] = r0*WC[idx] + r1*WC[1440+idx] + r2*WC[2880+idx] + r3*WC[4320+idx];
        }
        __syncthreads();

        for (int idx = tid; idx < 45*45; idx += 256) {
            int q = idx / 45, r = idx % 45;
            float a0 = 0.f, a1 = 0.f;
            #pragma unroll
            for (int k = 0; k < 32; k += 2) {
                a0 += wcm[k*45+q]*wem[k*45+r];
                a1 += wcm[(k+1)*45+q]*wem[(k+1)*45+r];
            }
            G2s[idx] = a0 + a1;
        }
        __syncthreads();

        if (tid < 225) {
            const int qzl_t[5] = {2,1,0,0,0}, qzh_t[5] = {4,4,4,3,2};
            const int q3l_t[3] = {0,1,0},     q3h_t[3] = {2,2,1};
            int cls = bid;
            int zc = cls / 9, yc = (cls % 9) / 3, xc = cls % 3;
            int s = tid;
            int sz = s / 25, sy = (s % 25) / 5, sx = s % 5;
            int qzl = max(qzl_t[zc], sz-4), qzh = min(qzh_t[zc], sz);
            int qyl = max(q3l_t[yc], sy-2), qyh = min(q3h_t[yc], sy);
            int qxl = max(q3l_t[xc], sx-2), qxh = min(q3h_t[xc], sx);
            float acc = 0.f;
            for (int qz = qzl; qz <= qzh; qz++) {
                const float* Gz = G2s + qz*9*45 + (sz-qz)*9;
                for (int qy = qyl; qy <= qyh; qy++) {
                    const float* Gy = Gz + qy*3*45 + (sy-qy)*3;
                    for (int qx = qxl; qx <= qxh; qx++)
                        acc += Gy[qx*45 + (sx-qx)];
                }
            }
            d_gcls[cls*225 + s] = acc;
        }
    } else {
        int p = bid - 45;
        float r0 = r2s[p][0], r1 = r2s[p][1], r2 = r2s[p][2], r3 = r2s[p][3];
        for (int ij = tid; ij < 961; ij += 256)
            d_Mp[p*961 + ij] = r0*W2[ij] + r1*W2[961+ij] + r2*W2[2*961+ij] + r3*W2[3*961+ij];
        if (p == 0 && tid < 8) d_offp[tid] = offs_s[tid];
    }
}

// ============================ fused: bilinear + pipelined 2-pass packed conv + mix ============================
#define NT    432             // 12*36 taps
#define DSTR  36
#define TILE_F (NT*DSTR)      // 15552
#define WCLS_F (4*5*225)      // 4500
#define MROW   32
#define MPS_F  (4*31*MROW)    // 3968
#define SMEM_F (TILE_F + WCLS_F + MPS_F + 8)

// pass0 v access: global ve index j in [2,11] -> depth pair j-2 in buf[5]
#define PV(B, j) ((((j) & 1) == 0) ? B[((j)-2) >> 1].x : B[((j)-2) >> 1].y)
// pass1 v access: global ve index j in [8,17] -> local pair j-8 in buf[5]
#define QV(B, j) ((((j) & 1) == 0) ? B[((j)-8) >> 1].x : B[((j)-8) >> 1].y)

// load pass-0 window (depth pairs 0..9) / pass-1 window (pairs 6..15)
#define LD0(B, tp) { B[0]=*(const ulonglong2*)(tp);      B[1]=*(const ulonglong2*)((tp)+4);  \
                     B[2]=*(const ulonglong2*)((tp)+8);  B[3]=*(const ulonglong2*)((tp)+12); \
                     B[4]=*(const ulonglong2*)((tp)+16); }
#define LD1(B, tp) { B[0]=*(const ulonglong2*)((tp)+12); B[1]=*(const ulonglong2*)((tp)+16); \
                     B[2]=*(const ulonglong2*)((tp)+20); B[3]=*(const ulonglong2*)((tp)+24); \
                     B[4]=*(const ulonglong2*)((tp)+28); }
#define ADV(tp, c) { tp += DSTR; if (++c == 5) { c = 0; tp += DSTR*31; } }

__device__ __forceinline__ void pass0_tap(const ulonglong2 v[5], const float* gt,
                                          ull accE[8], ull accO[7], float& acc0x)
{
    #pragma unroll
    for (int szh = 0; szh < 5; szh++) {
        const int sz = 2*szh;
        float gi = gt[450 + sz*25];
        ull wII = pk2(gi, gi);
        if (szh >= 2)
            fma2(accE[0], PV(v, szh), pk2(gt[sz*25], gt[225 + sz*25]));
        #pragma unroll
        for (int k = 1; k <= 7; k++) {
            if (!(k == 1 && szh == 0))
                fma2(accE[k], PV(v, k+szh), wII);
        }
    }
    #pragma unroll
    for (int szh = 0; szh < 4; szh++) {
        const int sz = 2*szh + 1;
        const int h = szh + 1;
        float gi = gt[450 + sz*25];
        ull wII = pk2(gi, gi);
        if (sz >= 3)
            fma2(accO[0], PV(v, h), pk2(gt[225 + sz*25], gi));
        #pragma unroll
        for (int k = 1; k <= 6; k++)
            fma2(accO[k], PV(v, k+h), wII);
        if (sz >= 5)
            acc0x += gt[sz*25] * upk(PV(v, szh)).y;
    }
}

__device__ __forceinline__ void pass1_tap(const ulonglong2 v[5], const float* gt,
                                          ull accE[8], ull accO[8])
{
    #pragma unroll
    for (int szh = 0; szh < 5; szh++) {
        const int sz = 2*szh;
        float gi = gt[450 + sz*25];
        ull wII = pk2(gi, gi);
        #pragma unroll
        for (int k = 8; k <= 13; k++)
            fma2(accE[k-8], QV(v, k+szh), wII);
        if (szh <= 2)
            fma2(accE[6], QV(v, 14+szh), pk2(gi, gt[675 + sz*25]));
        else if (szh == 3)
            fma2(accE[6], QV(v, 17), pk2(gi, 0.f));
        if (szh <= 2)
            fma2(accE[7], QV(v, 15+szh), pk2(gt[900 + sz*25], 0.f));
    }
    #pragma unroll
    for (int szh = 0; szh < 4; szh++) {
        const int sz = 2*szh + 1;
        const int h = szh + 1;
        float gi = gt[450 + sz*25];
        ull wII = pk2(gi, gi);
        #pragma unroll
        for (int k = 7; k <= 13; k++)
            fma2(accO[k-7], QV(v, k+h), wII);
        if (szh <= 1)
            fma2(accO[7], QV(v, 14+h), pk2(gt[675 + sz*25], gt[900 + sz*25]));
        else if (szh == 2)
            fma2(accO[7], QV(v, 17), pk2(gt[675 + sz*25], 0.f));
    }
}

__global__ __launch_bounds__(256, 2) void kfused(const float* __restrict__ x,
                                                 float* __restrict__ out)
{
    extern __shared__ float sm[];
    float* tile = sm;
    float* wcls = sm + TILE_F;
    float* Mps  = sm + TILE_F + WCLS_F;
    float* offs = Mps + MPS_F;

    int tx = threadIdx.x, ty = threadIdx.y;
    int tid = ty*32 + tx;
    int gx0 = blockIdx.x*32 - 2, gy0 = blockIdx.y*8 - 2;

    if (tid < 8) offs[tid] = d_offp[tid];
    int oylo = blockIdx.y*8, oxlo = blockIdx.x*32;
    int yec = (oylo == 0) ? 1 : ((oylo + 7 >= HO-1) ? 2 : 0);
    int xec = (oxlo == 0) ? 1 : ((oxlo + 31 >= WO-1) ? 2 : 0);

    for (int t = tid; t < WCLS_F; t += 256) {
        int slot = t / 1125, r = t % 1125;
        int ys = (slot & 1) ? yec : 0;
        int xs = (slot & 2) ? xec : 0;
        int zc = r / 225;
        wcls[t] = d_gcls[((zc*3 + ys)*3 + xs)*225 + (r % 225)];
    }
    for (int t = tid; t < MPS_F; t += 256) {
        int p = t / (31*MROW), r = t % (31*MROW);
        int ii = r / MROW, jj = r % MROW;
        Mps[t] = (jj < 31) ? d_Mp[p*961 + ii*31 + jj] : 0.f;
    }
    __syncthreads();

    // ---- bilinear halo tile from x (vectorized STS.128, depth-contiguous) ----
    for (int t = tid; t < NT; t += 256) {
        int yy = t / 36, xx = t % 36;
        int gy = gy0 + yy, gx = gx0 + xx;
        float* dst = tile + t*DSTR;
        if (gy < 0 || gy >= HO || gx < 0 || gx >= WO) {
            #pragma unroll
            for (int g = 0; g < 8; g++)
                *(float4*)(dst + 4*g) = make_float4(0.f, 0.f, 0.f, 0.f);
        } else {
            int p = ((gy & 1) << 1) | (gx & 1);
            float ix = (gx + 0.5f)*0.5f - 0.5f + offs[p*2+0];
            float iy = (gy + 0.5f)*0.5f - 0.5f + offs[p*2+1];
            float x0f = floorf(ix), y0f = floorf(iy);
            float wx1 = ix - x0f, wy1 = iy - y0f;
            int x0 = (int)x0f, y0 = (int)y0f;
            float vx0 = (x0   >= 0 && x0   <= WI-1) ? 1.f : 0.f;
            float vx1 = (x0+1 >= 0 && x0+1 <= WI-1) ? 1.f : 0.f;
            float vy0 = (y0   >= 0 && y0   <= HI-1) ? 1.f : 0.f;
            float vy1 = (y0+1 >= 0 && y0+1 <= HI-1) ? 1.f : 0.f;
            int xi0 = min(max(x0,   0), WI-1), xi1 = min(max(x0+1, 0), WI-1);
            int yi0 = min(max(y0,   0), HI-1), yi1 = min(max(y0+1, 0), HI-1);
            float w00 = (1.f-wy1)*(1.f-wx1)*vy0*vx0;
            float w01 = (1.f-wy1)*wx1*vy0*vx1;
            float w10 = wy1*(1.f-wx1)*vy1*vx0;
            float w11 = wy1*wx1*vy1*vx1;
            int b00 = yi0*WI + xi0, b01 = yi0*WI + xi1;
            int b10 = yi1*WI + xi0, b11 = yi1*WI + xi1;
            #pragma unroll 2
            for (int g = 0; g < 8; g++) {
                float4 buf;
                float v0, v1, v2, v3;
                {
                    const float* xc = x + (4*g+0)*(HI*WI);
                    v0 = w00*__ldg(xc+b00) + w01*__ldg(xc+b01)
                       + w10*__ldg(xc+b10) + w11*__ldg(xc+b11);
                }
                {
                    const float* xc = x + (4*g+1)*(HI*WI);
                    v1 = w00*__ldg(xc+b00) + w01*__ldg(xc+b01)
                       + w10*__ldg(xc+b10) + w11*__ldg(xc+b11);
                }
                {
                    const float* xc = x + (4*g+2)*(HI*WI);
                    v2 = w00*__ldg(xc+b00) + w01*__ldg(xc+b01)
                       + w10*__ldg(xc+b10) + w11*__ldg(xc+b11);
                }
                if (g < 7) {
                    const float* xc = x + (4*g+3)*(HI*WI);
                    v3 = w00*__ldg(xc+b00) + w01*__ldg(xc+b01)
                       + w10*__ldg(xc+b10) + w11*__ldg(xc+b11);
                } else {
                    v3 = 0.f;   // depth 31 pad
                }
                buf.x = v0; buf.y = v1; buf.z = v2; buf.w = v3;
                *(float4*)(dst + 4*g) = buf;
            }
        }
    }
    __syncthreads();

    int oy = blockIdx.y*8 + ty, ox = blockIdx.x*32 + tx;
    int yfl = (oy == 0 || oy == HO-1) ? 1 : 0;
    int xfl = (ox == 0 || ox == WO-1) ? 1 : 0;
    const float* gY = wcls + (yfl + 2*xfl)*1125;
    const float* ctr = tile + ((ty+2)*36 + (tx+2))*DSTR;
    const float* tbase = tile + (ty*36 + tx)*DSTR;

    float a[32];

    // ================= PASS 0: depths 0..15 (pipelined) =================
    {
        ull accE[8], accO[7];
        float acc0x = 0.f;
        #pragma unroll
        for (int k = 0; k < 8; k++) accE[k] = *(const ull*)(ctr + 2*k);  // residual
        #pragma unroll
        for (int k = 0; k < 7; k++) accO[k] = 0ULL;

        ulonglong2 bA[5], bB[5];
        const float* tp = tbase; int c = 0;
        const float* gtp = gY;
        LD0(bA, tp); ADV(tp, c);
        #pragma unroll 1
        for (int tt = 0; tt < 12; tt++) {
            LD0(bB, tp); ADV(tp, c);
            pass0_tap(bA, gtp, accE, accO, acc0x); gtp++;
            LD0(bA, tp); ADV(tp, c);
            pass0_tap(bB, gtp, accE, accO, acc0x); gtp++;
        }
        pass0_tap(bA, gtp, accE, accO, acc0x);

        #pragma unroll
        for (int k = 0; k < 8; k++) { float2 e = upk(accE[k]); a[2*k] = e.x; a[2*k+1] = e.y; }
        #pragma unroll
        for (int k = 0; k < 7; k++) { float2 o = upk(accO[k]); a[2*k+1] += o.x; a[2*k+2] += o.y; }
        a[0] += acc0x;
    }

    // ================= PASS 1: depths 16..31 (+ finish d15) (pipelined) =================
    {
        ull accE[8], accO[8];
        #pragma unroll
        for (int k = 0; k < 8; k++) accE[k] = *(const ull*)(ctr + 16 + 2*k);  // residual d16..31
        #pragma unroll
        for (int k = 0; k < 8; k++) accO[k] = 0ULL;

        ulonglong2 bA[5], bB[5];
        const float* tp = tbase; int c = 0;
        const float* gtp = gY;
        LD1(bA, tp); ADV(tp, c);
        #pragma unroll 1
        for (int tt = 0; tt < 12; tt++) {
            LD1(bB, tp); ADV(tp, c);
            pass1_tap(bA, gtp, accE, accO); gtp++;
            LD1(bA, tp); ADV(tp, c);
            pass1_tap(bB, gtp, accE, accO); gtp++;
        }
        pass1_tap(bA, gtp, accE, accO);

        #pragma unroll
        for (int k = 0; k < 8; k++) { float2 e = upk(accE[k]); a[16+2*k] = e.x; a[17+2*k] = e.y; }
        { float2 o = upk(accO[0]); a[15] += o.x; a[16] += o.y; }
        #pragma unroll
        for (int k = 1; k < 8; k++) { float2 o = upk(accO[k]); a[15+2*k] += o.x; a[16+2*k] += o.y; }
    }
    a[31] = 0.f;

    // per-pixel channel mix + fea0 (float4 reads of padded M rows)
    const float* M = Mps + (((oy & 1) << 1) | (ox & 1))*(31*MROW);
    int pix = oy*WO + ox;
    #pragma unroll 1
    for (int ii = 0; ii < 30; ii += 2) {
        const float* M0 = M + ii*MROW;
        const float* M1 = M0 + MROW;
        float s00 = 0.f, s01 = 0.f, s10 = 0.f, s11 = 0.f;
        #pragma unroll
        for (int jc = 0; jc < 8; jc += 2) {
            float4 a0 = *(const float4*)(M0 + jc*4);
            float4 b0 = *(const float4*)(M0 + jc*4 + 4);
            float4 a1 = *(const float4*)(M1 + jc*4);
            float4 b1 = *(const float4*)(M1 + jc*4 + 4);
            int j0 = jc*4;
            s00 += a0.x*a[j0+0] + a0.y*a[j0+1] + a0.z*a[j0+2] + a0.w*a[j0+3];
            s01 += b0.x*a[j0+4] + b0.y*a[j0+5] + b0.z*a[j0+6] + b0.w*a[j0+7];
            s10 += a1.x*a[j0+0] + a1.y*a[j0+1] + a1.z*a[j0+2] + a1.w*a[j0+3];
            s11 += b1.x*a[j0+4] + b1.y*a[j0+5] + b1.z*a[j0+6] + b1.w*a[j0+7];
        }
        out[ii*NPIX + pix]     = ctr[ii]   + (s00 + s01);
        out[(ii+1)*NPIX + pix] = ctr[ii+1] + (s10 + s11);
    }
    {
        const float* M0 = M + 30*MROW;
        float s0 = 0.f, s1 = 0.f;
        #pragma unroll
        for (int jc = 0; jc < 8; jc += 2) {
            float4 a0 = *(const float4*)(M0 + jc*4);
            float4 b0 = *(const float4*)(M0 + jc*4 + 4);
            int j0 = jc*4;
            s0 += a0.x*a[j0+0] + a0.y*a[j0+1] + a0.z*a[j0+2] + a0.w*a[j0+3];
            s1 += b0.x*a[j0+4] + b0.y*a[j0+5] + b0.z*a[j0+6] + b0.w*a[j0+7];
        }
        out[30*NPIX + pix] = ctr[30] + (s0 + s1);
    }
}

// ============================ launch ============================
extern "C" void kernel_launch(void* const* d_in, const int* in_sizes, int n_in,
                              void* d_out, int out_size)
{
    const float* x   = (const float*)d_in[0];
    // d_in[1] = scale (always 2; parity tables assume it)
    const float* WE  = (const float*)d_in[2];
    const float* WC  = (const float*)d_in[3];
    const float* W2  = (const float*)d_in[4];
    const float* bw1 = (const float*)d_in[5];
    const float* bb1 = (const float*)d_in[6];
    const float* bw2 = (const float*)d_in[7];
    const float* bb2 = (const float*)d_in[8];
    const float* r2w = (const float*)d_in[9];
    const float* r2b = (const float*)d_in[10];
    const float* ow  = (const float*)d_in[11];
    const float* ob  = (const float*)d_in[12];
    const float* l1w = (const float*)d_in[13];
    const float* l1b = (const float*)d_in[14];
    const float* l2w = (const float*)d_in[15];
    const float* l2b = (const float*)d_in[16];
    float* out = (float*)d_out;

    static int smem_set = 0;
    if (!smem_set) {
        cudaFuncSetAttribute(kfused, cudaFuncAttributeMaxDynamicSharedMemorySize,
                             SMEM_F * (int)sizeof(float));
        smem_set = 1;
    }

    k0<<<49, 256>>>(WE, WC, W2, bw1, bb1, bw2, bb2,
                    r2w, r2b, ow, ob, l1w, l1b, l2w, l2b);
    kfused<<<dim3(WO/32, HO/8), dim3(32, 8), SMEM_F*(int)sizeof(float)>>>(x, out);
}

// round 14
// speedup vs baseline: 1.0941x; 1.0038x over previous
#include <cuda_runtime.h>
#include <math.h>

#define CC 31
#define HO 256
#define WO 256
#define NPIX (HO*WO)          // 65536
#define HI 128
#define WI 128

typedef unsigned long long ull;

__device__ __forceinline__ ull pk2(float lo, float hi) {
    ull r; asm("mov.b64 %0,{%1,%2};" : "=l"(r) : "f"(lo), "f"(hi)); return r;
}
__device__ __forceinline__ void fma2(ull& d, ull a, ull b) {
    asm("fma.rn.f32x2 %0,%1,%2,%0;" : "+l"(d) : "l"(a), "l"(b));
}
__device__ __forceinline__ float2 upk(ull v) {
    float2 r; asm("mov.b64 {%0,%1},%2;" : "=f"(r.x), "=f"(r.y) : "l"(v)); return r;
}

// ---------------- static device scratch ----------------
__device__ float d_gcls[5*3*3*225]; // 45 boundary-class composed 9x5x5 kernels
__device__ float d_Mp[4*961];       // per-parity 31x31 mixing matrices
__device__ int   d_done;            // worker completion counter (memset to 0 per launch)

// ============================ single fused kernel ============================
#define NT    432             // 12*36 taps
#define DSTR  36
#define TILE_F (NT*DSTR)      // 15552
#define WCLS_F (4*5*225)      // 4500
#define MROW   32
#define MPS_F  (4*31*MROW)    // 3968
#define SMEM_F (TILE_F + WCLS_F + MPS_F + 8)

// Phase-A scratch inside tile region (dead before bilinear build)
#define SCR_BW2 0             // 4096
#define SCR_WEM 4096          // 1440
#define SCR_WCM 5536          // 1440
#define SCR_G2  6976          // 2025  (ends 9001 < 15552)

// VE(j): packed depth pair (2(j-2), 2(j-2)+1) from the vq[] ull2 registers.
#define VE(j) ((((j) & 1) == 0) ? vq[((j)-2) >> 1].x : vq[((j)-2) >> 1].y)

__global__ __launch_bounds__(256, 2) void kall(
    const float* __restrict__ x,
    const float* __restrict__ WE,  // (4,32,1,5,3,3) = 4*1440
    const float* __restrict__ WC,
    const float* __restrict__ W2,  // (4,31,31)
    const float* __restrict__ bw1, const float* __restrict__ bb1,
    const float* __restrict__ bw2, const float* __restrict__ bb2,
    const float* __restrict__ r2w, const float* __restrict__ r2b,
    const float* __restrict__ ow,  const float* __restrict__ ob,
    const float* __restrict__ l1w, const float* __restrict__ l1b,
    const float* __restrict__ l2w, const float* __restrict__ l2b,
    float* __restrict__ out)
{
    extern __shared__ float sm[];
    float* tile = sm;
    float* wcls = sm + TILE_F;
    float* Mps  = sm + TILE_F + WCLS_F;
    float* offs = Mps + MPS_F;

    __shared__ float s_bw1[192], s_bb1[64], s_bb2[64];
    __shared__ float s_r2w[256], s_r2b[4], s_ow[128], s_ob[2];
    __shared__ float s_l1w[128], s_l1b[64], s_l2w[256], s_l2b[4];
    __shared__ float e1s[4][64], e2s[4][64];
    __shared__ float h1s[2][64], lgs[2][4];
    __shared__ float r2s[4][4], rsum_s[4];

    int tx = threadIdx.x, ty = threadIdx.y;
    int tid = ty*32 + tx;
    int bflat = blockIdx.y*gridDim.x + blockIdx.x;

    // ============ Phase A-lite (ALL blocks): tiny MLP -> offs, r2s, rsum ============
    for (int t = tid; t < 4096; t += 256) tile[SCR_BW2 + t] = bw2[t];
    for (int t = tid; t < 192;  t += 256) s_bw1[t] = bw1[t];
    for (int t = tid; t < 64;   t += 256) { s_bb1[t] = bb1[t]; s_bb2[t] = bb2[t];
                                            s_l1b[t] = l1b[t]; }
    for (int t = tid; t < 256;  t += 256) { s_r2w[t] = r2w[t]; s_l2w[t] = l2w[t]; }
    for (int t = tid; t < 128;  t += 256) { s_ow[t] = ow[t]; s_l1w[t] = l1w[t]; }
    if (tid < 4) { s_r2b[tid] = r2b[tid]; s_l2b[tid] = l2b[tid]; }
    if (tid < 2) s_ob[tid] = ob[tid];
    __syncthreads();

    {
        int p = tid >> 6, o = tid & 63;
        float ch = (p & 2) ? 0.25f : -0.25f;
        float cw = (p & 1) ? 0.25f : -0.25f;
        float a = s_bw1[o*3+0]*0.5f + s_bw1[o*3+1]*ch + s_bw1[o*3+2]*cw + s_bb1[o];
        e1s[p][o] = a > 0.f ? a : 0.f;
    }
    if (tid < 128) {
        int r = tid >> 6, o = tid & 63;
        float chr = r ? 0.25f : -0.25f;
        float a = s_l1w[o*2+0]*0.5f + s_l1w[o*2+1]*chr + s_l1b[o];
        h1s[r][o] = a > 0.f ? a : 0.f;
    }
    __syncthreads();

    {
        int p = tid >> 6, o = tid & 63;
        float a = s_bb2[o];
        #pragma unroll 8
        for (int i = 0; i < 64; i++) a += tile[SCR_BW2 + o*64+i]*e1s[p][i];
        e2s[p][o] = a > 0.f ? a : 0.f;
    }
    if (tid < 8) {
        int r = tid >> 2, e = tid & 3;
        float a = s_l2b[e];
        #pragma unroll 8
        for (int o = 0; o < 64; o++) a += s_l2w[e*64+o]*h1s[r][o];
        lgs[r][e] = a;
    }
    __syncthreads();

    if (tid < 24) {
        int p = tid / 6, u = tid % 6;
        if (u < 2) {
            float a = s_ob[u];
            for (int i = 0; i < 64; i++) a += s_ow[u*64+i]*e2s[p][i];
            offs[p*2+u] = a;
        } else {
            int e = u - 2;
            float a = s_r2b[e];
            for (int i = 0; i < 64; i++) a += s_r2w[e*64+i]*e2s[p][i];
            r2s[p][e] = 1.f/(1.f+expf(-a));
        }
    }
    if (tid >= 32 && tid < 36) {
        int e = tid - 32;
        float rsv = 0.f;
        #pragma unroll
        for (int r = 0; r < 2; r++) {
            float m = fmaxf(fmaxf(lgs[r][0], lgs[r][1]), fmaxf(lgs[r][2], lgs[r][3]));
            float s = 0.f;
            #pragma unroll
            for (int j = 0; j < 4; j++) s += expf(lgs[r][j]-m);
            rsv += expf(lgs[r][e]-m)/s;
        }
        rsum_s[e] = rsv;
    }
    __syncthreads();

    // ============ Worker blocks publish gcls / Mp ============
    if (bflat < 45) {
        float r0 = rsum_s[0], r1 = rsum_s[1], r2 = rsum_s[2], r3 = rsum_s[3];
        for (int idx = tid; idx < 32*45; idx += 256) {
            tile[SCR_WEM + idx] = r0*WE[idx] + r1*WE[1440+idx]
                                + r2*WE[2880+idx] + r3*WE[4320+idx];
            tile[SCR_WCM + idx] = r0*WC[idx] + r1*WC[1440+idx]
                                + r2*WC[2880+idx] + r3*WC[4320+idx];
        }
        __syncthreads();
        for (int idx = tid; idx < 45*45; idx += 256) {
            int q = idx / 45, r = idx % 45;
            float a0 = 0.f, a1 = 0.f;
            #pragma unroll
            for (int k = 0; k < 32; k += 2) {
                a0 += tile[SCR_WCM + k*45+q]*tile[SCR_WEM + k*45+r];
                a1 += tile[SCR_WCM + (k+1)*45+q]*tile[SCR_WEM + (k+1)*45+r];
            }
            tile[SCR_G2 + idx] = a0 + a1;
        }
        __syncthreads();
        if (tid < 225) {
            const int qzl_t[5] = {2,1,0,0,0}, qzh_t[5] = {4,4,4,3,2};
            const int q3l_t[3] = {0,1,0},     q3h_t[3] = {2,2,1};
            int cls = bflat;
            int zc = cls / 9, yc = (cls % 9) / 3, xc = cls % 3;
            int s = tid;
            int sz = s / 25, sy = (s % 25) / 5, sx = s % 5;
            int qzl = max(qzl_t[zc], sz-4), qzh = min(qzh_t[zc], sz);
            int qyl = max(q3l_t[yc], sy-2), qyh = min(q3h_t[yc], sy);
            int qxl = max(q3l_t[xc], sx-2), qxh = min(q3h_t[xc], sx);
            float acc = 0.f;
            for (int qz = qzl; qz <= qzh; qz++) {
                const float* Gz = tile + SCR_G2 + qz*9*45 + (sz-qz)*9;
                for (int qy = qyl; qy <= qyh; qy++) {
                    const float* Gy = Gz + qy*3*45 + (sy-qy)*3;
                    for (int qx = qxl; qx <= qxh; qx++)
                        acc += Gy[qx*45 + (sx-qx)];
                }
            }
            d_gcls[cls*225 + s] = acc;
        }
        __threadfence();
        __syncthreads();
        if (tid == 0) atomicAdd(&d_done, 1);
    } else if (bflat < 49) {
        int p = bflat - 45;
        float r0 = r2s[p][0], r1 = r2s[p][1], r2 = r2s[p][2], r3 = r2s[p][3];
        for (int ij = tid; ij < 961; ij += 256)
            d_Mp[p*961 + ij] = r0*W2[ij] + r1*W2[961+ij]
                             + r2*W2[2*961+ij] + r3*W2[3*961+ij];
        __threadfence();
        __syncthreads();
        if (tid == 0) atomicAdd(&d_done, 1);
    }
    __syncthreads();   // scratch in tile region dead; offs stays live

    // ============ bilinear halo tile (overlaps with workers elsewhere) ============
    int gx0 = blockIdx.x*32 - 2, gy0 = blockIdx.y*8 - 2;
    for (int t = tid; t < NT; t += 256) {
        int yy = t / 36, xx = t % 36;
        int gy = gy0 + yy, gx = gx0 + xx;
        float* dst = tile + t*DSTR;
        if (gy < 0 || gy >= HO || gx < 0 || gx >= WO) {
            #pragma unroll
            for (int g = 0; g < 8; g++)
                *(float4*)(dst + 4*g) = make_float4(0.f, 0.f, 0.f, 0.f);
        } else {
            int p = ((gy & 1) << 1) | (gx & 1);
            float ix = (gx + 0.5f)*0.5f - 0.5f + offs[p*2+0];
            float iy = (gy + 0.5f)*0.5f - 0.5f + offs[p*2+1];
            float x0f = floorf(ix), y0f = floorf(iy);
            float wx1 = ix - x0f, wy1 = iy - y0f;
            int x0 = (int)x0f, y0 = (int)y0f;
            float vx0 = (x0   >= 0 && x0   <= WI-1) ? 1.f : 0.f;
            float vx1 = (x0+1 >= 0 && x0+1 <= WI-1) ? 1.f : 0.f;
            float vy0 = (y0   >= 0 && y0   <= HI-1) ? 1.f : 0.f;
            float vy1 = (y0+1 >= 0 && y0+1 <= HI-1) ? 1.f : 0.f;
            int xi0 = min(max(x0,   0), WI-1), xi1 = min(max(x0+1, 0), WI-1);
            int yi0 = min(max(y0,   0), HI-1), yi1 = min(max(y0+1, 0), HI-1);
            float w00 = (1.f-wy1)*(1.f-wx1)*vy0*vx0;
            float w01 = (1.f-wy1)*wx1*vy0*vx1;
            float w10 = wy1*(1.f-wx1)*vy1*vx0;
            float w11 = wy1*wx1*vy1*vx1;
            int b00 = yi0*WI + xi0, b01 = yi0*WI + xi1;
            int b10 = yi1*WI + xi0, b11 = yi1*WI + xi1;
            #pragma unroll 2
            for (int g = 0; g < 8; g++) {
                float4 buf;
                float v0, v1, v2, v3;
                {
                    const float* xc = x + (4*g+0)*(HI*WI);
                    v0 = w00*__ldg(xc+b00) + w01*__ldg(xc+b01)
                       + w10*__ldg(xc+b10) + w11*__ldg(xc+b11);
                }
                {
                    const float* xc = x + (4*g+1)*(HI*WI);
                    v1 = w00*__ldg(xc+b00) + w01*__ldg(xc+b01)
                       + w10*__ldg(xc+b10) + w11*__ldg(xc+b11);
                }
                {
                    const float* xc = x + (4*g+2)*(HI*WI);
                    v2 = w00*__ldg(xc+b00) + w01*__ldg(xc+b01)
                       + w10*__ldg(xc+b10) + w11*__ldg(xc+b11);
                }
                if (g < 7) {
                    const float* xc = x + (4*g+3)*(HI*WI);
                    v3 = w00*__ldg(xc+b00) + w01*__ldg(xc+b01)
                       + w10*__ldg(xc+b10) + w11*__ldg(xc+b11);
                } else {
                    v3 = 0.f;   // depth 31 pad
                }
                buf.x = v0; buf.y = v1; buf.z = v2; buf.w = v3;
                *(float4*)(dst + 4*g) = buf;
            }
        }
    }

    // ============ wait for workers, then stage wcls/Mps ============
    if (tid == 0) {
        while (*((volatile int*)&d_done) < 49) __nanosleep(128);
    }
    __syncthreads();
    __threadfence();   // order subsequent global reads after flag observation

    int oylo = blockIdx.y*8, oxlo = blockIdx.x*32;
    int yec = (oylo == 0) ? 1 : ((oylo + 7 >= HO-1) ? 2 : 0);
    int xec = (oxlo == 0) ? 1 : ((oxlo + 31 >= WO-1) ? 2 : 0);
    int slot_mask = 1 | ((yec ? 1 : 0) << 1) | ((xec ? 1 : 0) << 2)
                  | (((yec && xec) ? 1 : 0) << 3);
    #pragma unroll 1
    for (int slot = 0; slot < 4; slot++) {
        if (!((slot_mask >> slot) & 1)) continue;
        int ys = (slot & 1) ? yec : 0;
        int xs = (slot & 2) ? xec : 0;
        for (int r = tid; r < 1125; r += 256) {
            int zc = r / 225;
            wcls[slot*1125 + r] = d_gcls[((zc*3 + ys)*3 + xs)*225 + (r % 225)];
        }
    }
    for (int t = tid; t < MPS_F; t += 256) {
        int p = t / (31*MROW), r = t % (31*MROW);
        int ii = r / MROW, jj = r % MROW;
        Mps[t] = (jj < 31) ? d_Mp[p*961 + ii*31 + jj] : 0.f;
    }
    __syncthreads();

    // ============ conv (R11 merged packed) + mix ============
    int oy = blockIdx.y*8 + ty, ox = blockIdx.x*32 + tx;
    int yfl = (oy == 0 || oy == HO-1) ? 1 : 0;
    int xfl = (ox == 0 || ox == WO-1) ? 1 : 0;
    const float* gY = wcls + (yfl + 2*xfl)*1125;
    const float* ctr = tile + ((ty+2)*36 + (tx+2))*DSTR;

    ull accE[16], accO[15];
    float acc0x = 0.f;
    #pragma unroll
    for (int k = 0; k < 16; k++) accE[k] = *(const ull*)(ctr + 2*k);   // residual init
    #pragma unroll
    for (int k = 0; k < 15; k++) accO[k] = 0ULL;

    #pragma unroll 1
    for (int sy = 0; sy < 5; sy++) {
        #pragma unroll 1
        for (int sx = 0; sx < 5; sx++) {
            const float* tp = tile + ((ty+sy)*36 + (tx+sx))*DSTR;
            const float* gt = gY + sy*5 + sx;   // + zc*225 + sz*25
            ulonglong2 vq[8];
            #pragma unroll
            for (int m = 0; m < 8; m++) vq[m] = *(const ulonglong2*)(tp + 4*m);

            // ---- even sz (accE: pairs (2k,2k+1)) ----
            #pragma unroll
            for (int szh = 0; szh < 5; szh++) {
                const int sz = 2*szh;
                float gi = gt[450 + sz*25];
                ull wII = pk2(gi, gi);
                if (szh >= 2) {
                    fma2(accE[0], VE(szh), pk2(gt[sz*25], gt[225 + sz*25]));
                }
                #pragma unroll
                for (int k = 1; k <= 13; k++) {
                    if (!(k == 1 && szh == 0))
                        fma2(accE[k], VE(k+szh), wII);
                }
                if (szh <= 2) {
                    fma2(accE[14], VE(14+szh), pk2(gi, gt[675 + sz*25]));
                } else if (szh == 3) {
                    fma2(accE[14], VE(17), pk2(gi, 0.f));
                }
                if (szh <= 2) {
                    fma2(accE[15], VE(15+szh), pk2(gt[900 + sz*25], 0.f));
                }
            }
            // ---- odd sz (accO: pairs (2k+1,2k+2)) ----
            #pragma unroll
            for (int szh = 0; szh < 4; szh++) {
                const int sz = 2*szh + 1;
                const int h = szh + 1;
                float gi = gt[450 + sz*25];
                ull wII = pk2(gi, gi);
                if (sz >= 3) {
                    fma2(accO[0], VE(h), pk2(gt[225 + sz*25], gi));
                }
                #pragma unroll
                for (int k = 1; k <= 13; k++)
                    fma2(accO[k], VE(k+h), wII);
                if (sz <= 3) {
                    fma2(accO[14], VE(14+h), pk2(gt[675 + sz*25], gt[900 + sz*25]));
                } else if (sz == 5) {
                    fma2(accO[14], VE(17), pk2(gt[675 + sz*25], 0.f));
                }
                if (sz >= 5) {
                    acc0x += gt[sz*25] * upk(VE(szh)).y;
                }
            }
        }
    }

    float a[32];
    #pragma unroll
    for (int k = 0; k < 16; k++) { float2 e = upk(accE[k]); a[2*k] = e.x; a[2*k+1] = e.y; }
    #pragma unroll
    for (int k = 0; k < 15; k++) { float2 o = upk(accO[k]); a[2*k+1] += o.x; a[2*k+2] += o.y; }
    a[0] += acc0x;
    a[31] = 0.f;

    const float* M = Mps + (((oy & 1) << 1) | (ox & 1))*(31*MROW);
    int pix = oy*WO + ox;
    #pragma unroll 1
    for (int ii = 0; ii < 30; ii += 2) {
        const float* M0 = M + ii*MROW;
        const float* M1 = M0 + MROW;
        float s00 = 0.f, s01 = 0.f, s10 = 0.f, s11 = 0.f;
        #pragma unroll
        for (int jc = 0; jc < 8; jc += 2) {
            float4 a0 = *(const float4*)(M0 + jc*4);
            float4 b0 = *(const float4*)(M0 + jc*4 + 4);
            float4 a1 = *(const float4*)(M1 + jc*4);
            float4 b1 = *(const float4*)(M1 + jc*4 + 4);
            int j0 = jc*4;
            s00 += a0.x*a[j0+0] + a0.y*a[j0+1] + a0.z*a[j0+2] + a0.w*a[j0+3];
            s01 += b0.x*a[j0+4] + b0.y*a[j0+5] + b0.z*a[j0+6] + b0.w*a[j0+7];
            s10 += a1.x*a[j0+0] + a1.y*a[j0+1] + a1.z*a[j0+2] + a1.w*a[j0+3];
            s11 += b1.x*a[j0+4] + b1.y*a[j0+5] + b1.z*a[j0+6] + b1.w*a[j0+7];
        }
        out[ii*NPIX + pix]     = ctr[ii]   + (s00 + s01);
        out[(ii+1)*NPIX + pix] = ctr[ii+1] + (s10 + s11);
    }
    {
        const float* M0 = M + 30*MROW;
        float s0 = 0.f, s1 = 0.f;
        #pragma unroll
        for (int jc = 0; jc < 8; jc += 2) {
            float4 a0 = *(const float4*)(M0 + jc*4);
            float4 b0 = *(const float4*)(M0 + jc*4 + 4);
            int j0 = jc*4;
            s0 += a0.x*a[j0+0] + a0.y*a[j0+1] + a0.z*a[j0+2] + a0.w*a[j0+3];
            s1 += b0.x*a[j0+4] + b0.y*a[j0+5] + b0.z*a[j0+6] + b0.w*a[j0+7];
        }
        out[30*NPIX + pix] = ctr[30] + (s0 + s1);
    }
}

// ============================ launch ============================
extern "C" void kernel_launch(void* const* d_in, const int* in_sizes, int n_in,
                              void* d_out, int out_size)
{
    const float* x   = (const float*)d_in[0];
    // d_in[1] = scale (always 2; parity tables assume it)
    const float* WE  = (const float*)d_in[2];
    const float* WC  = (const float*)d_in[3];
    const float* W2  = (const float*)d_in[4];
    const float* bw1 = (const float*)d_in[5];
    const float* bb1 = (const float*)d_in[6];
    const float* bw2 = (const float*)d_in[7];
    const float* bb2 = (const float*)d_in[8];
    const float* r2w = (const float*)d_in[9];
    const float* r2b = (const float*)d_in[10];
    const float* ow  = (const float*)d_in[11];
    const float* ob  = (const float*)d_in[12];
    const float* l1w = (const float*)d_in[13];
    const float* l1b = (const float*)d_in[14];
    const float* l2w = (const float*)d_in[15];
    const float* l2b = (const float*)d_in[16];
    float* out = (float*)d_out;

    static void* done_addr = nullptr;
    if (!done_addr) {
        cudaGetSymbolAddress(&done_addr, d_done);
        cudaFuncSetAttribute(kall, cudaFuncAttributeMaxDynamicSharedMemorySize,
                             SMEM_F * (int)sizeof(float));
    }

    cudaMemsetAsync(done_addr, 0, sizeof(int));
    kall<<<dim3(WO/32, HO/8), dim3(32, 8), SMEM_F*(int)sizeof(float)>>>(
        x, WE, WC, W2, bw1, bb1, bw2, bb2,
        r2w, r2b, ow, ob, l1w, l1b, l2w, l2b, out);
}

// round 15
// speedup vs baseline: 1.2500x; 1.1425x over previous
#include <cuda_runtime.h>
#include <math.h>

#define CC 31
#define HO 256
#define WO 256
#define NPIX (HO*WO)          // 65536
#define HI 128
#define WI 128

typedef unsigned long long ull;

__device__ __forceinline__ ull pk2(float lo, float hi) {
    ull r; asm("mov.b64 %0,{%1,%2};" : "=l"(r) : "f"(lo), "f"(hi)); return r;
}
__device__ __forceinline__ void fma2(ull& d, ull a, ull b) {
    asm("fma.rn.f32x2 %0,%1,%2,%0;" : "+l"(d) : "l"(a), "l"(b));
}
__device__ __forceinline__ float2 upk(ull v) {
    float2 r; asm("mov.b64 {%0,%1},%2;" : "=f"(r.x), "=f"(r.y) : "l"(v)); return r;
}

// ---------------- static device scratch ----------------
__device__ float d_gcls[5*3*3*225]; // 45 boundary-class composed 9x5x5 kernels
__device__ float d_Mp[4*961];       // per-parity 31x31 mixing matrices
__device__ float d_offp[8];         // per-parity offsets
__device__ int   d_flags[2];        // [0]=worker done count, [1]=offs ready (memset 0 per launch)

// ============================ single fused kernel ============================
#define NT    432             // 12*36 taps
#define DSTR  36
#define TILE_F (NT*DSTR)      // 15552
#define WCLS_F (4*5*225)      // 4500
#define MROW   32
#define MPS_F  (4*31*MROW)    // 3968
#define SMEM_F (TILE_F + WCLS_F + MPS_F + 8)

// Phase-A scratch inside tile region (dead before bilinear build)
#define SCR_BW2 0             // 4096
#define SCR_WEM 4096          // 1440
#define SCR_WCM 5536          // 1440
#define SCR_G2  6976          // 2025  (ends 9001 < 15552)

// VE(j): packed depth pair (2(j-2), 2(j-2)+1) from the vq[] ull2 registers.
#define VE(j) ((((j) & 1) == 0) ? vq[((j)-2) >> 1].x : vq[((j)-2) >> 1].y)

__global__ __launch_bounds__(256, 2) void kall(
    const float* __restrict__ x,
    const float* __restrict__ WE,  // (4,32,1,5,3,3) = 4*1440
    const float* __restrict__ WC,
    const float* __restrict__ W2,  // (4,31,31)
    const float* __restrict__ bw1, const float* __restrict__ bb1,
    const float* __restrict__ bw2, const float* __restrict__ bb2,
    const float* __restrict__ r2w, const float* __restrict__ r2b,
    const float* __restrict__ ow,  const float* __restrict__ ob,
    const float* __restrict__ l1w, const float* __restrict__ l1b,
    const float* __restrict__ l2w, const float* __restrict__ l2b,
    float* __restrict__ out)
{
    extern __shared__ float sm[];
    float* tile = sm;
    float* wcls = sm + TILE_F;
    float* Mps  = sm + TILE_F + WCLS_F;
    float* offs = Mps + MPS_F;

    __shared__ float s_small[1024];     // staging for whichever small weights a role needs
    __shared__ float e1s[4][64], e2s[4][64];
    __shared__ float h1s[2][64], lgs[2][4];
    __shared__ float r2s[4][4], rsum_s[4], offs_w[8];

    int tx = threadIdx.x, ty = threadIdx.y;
    int tid = ty*32 + tx;
    int bflat = blockIdx.y*gridDim.x + blockIdx.x;

    // ======================= WORKER PHASES =======================
    if (bflat < 45) {
        // ---- gcls worker: needs only routing MLP (l1*, l2*) for rsum ----
        float* sl1w = s_small;          // 128
        float* sl1b = s_small + 128;    // 64
        float* sl2w = s_small + 192;    // 256
        float* sl2b = s_small + 448;    // 4
        for (int t = tid; t < 128; t += 256) sl1w[t] = l1w[t];
        for (int t = tid; t < 64;  t += 256) sl1b[t] = l1b[t];
        for (int t = tid; t < 256; t += 256) sl2w[t] = l2w[t];
        if (tid < 4) sl2b[tid] = l2b[tid];
        __syncthreads();
        if (tid < 128) {
            int r = tid >> 6, o = tid & 63;
            float chr = r ? 0.25f : -0.25f;
            float a = sl1w[o*2+0]*0.5f + sl1w[o*2+1]*chr + sl1b[o];
            h1s[r][o] = a > 0.f ? a : 0.f;
        }
        __syncthreads();
        if (tid < 8) {
            int r = tid >> 2, e = tid & 3;
            float a = sl2b[e];
            #pragma unroll 8
            for (int o = 0; o < 64; o++) a += sl2w[e*64+o]*h1s[r][o];
            lgs[r][e] = a;
        }
        __syncthreads();
        if (tid < 4) {
            int e = tid;
            float rsv = 0.f;
            #pragma unroll
            for (int r = 0; r < 2; r++) {
                float m = fmaxf(fmaxf(lgs[r][0], lgs[r][1]), fmaxf(lgs[r][2], lgs[r][3]));
                float s = 0.f;
                #pragma unroll
                for (int j = 0; j < 4; j++) s += expf(lgs[r][j]-m);
                rsv += expf(lgs[r][e]-m)/s;
            }
            rsum_s[e] = rsv;
        }
        __syncthreads();

        float r0 = rsum_s[0], r1 = rsum_s[1], r2 = rsum_s[2], r3 = rsum_s[3];
        for (int idx = tid; idx < 32*45; idx += 256) {
            tile[SCR_WEM + idx] = r0*WE[idx] + r1*WE[1440+idx]
                                + r2*WE[2880+idx] + r3*WE[4320+idx];
            tile[SCR_WCM + idx] = r0*WC[idx] + r1*WC[1440+idx]
                                + r2*WC[2880+idx] + r3*WC[4320+idx];
        }
        __syncthreads();
        for (int idx = tid; idx < 45*45; idx += 256) {
            int q = idx / 45, r = idx % 45;
            float a0 = 0.f, a1 = 0.f;
            #pragma unroll
            for (int k = 0; k < 32; k += 2) {
                a0 += tile[SCR_WCM + k*45+q]*tile[SCR_WEM + k*45+r];
                a1 += tile[SCR_WCM + (k+1)*45+q]*tile[SCR_WEM + (k+1)*45+r];
            }
            tile[SCR_G2 + idx] = a0 + a1;
        }
        __syncthreads();
        if (tid < 225) {
            const int qzl_t[5] = {2,1,0,0,0}, qzh_t[5] = {4,4,4,3,2};
            const int q3l_t[3] = {0,1,0},     q3h_t[3] = {2,2,1};
            int cls = bflat;
            int zc = cls / 9, yc = (cls % 9) / 3, xc = cls % 3;
            int s = tid;
            int sz = s / 25, sy = (s % 25) / 5, sx = s % 5;
            int qzl = max(qzl_t[zc], sz-4), qzh = min(qzh_t[zc], sz);
            int qyl = max(q3l_t[yc], sy-2), qyh = min(q3h_t[yc], sy);
            int qxl = max(q3l_t[xc], sx-2), qxh = min(q3h_t[xc], sx);
            float acc = 0.f;
            for (int qz = qzl; qz <= qzh; qz++) {
                const float* Gz = tile + SCR_G2 + qz*9*45 + (sz-qz)*9;
                for (int qy = qyl; qy <= qyh; qy++) {
                    const float* Gy = Gz + qy*3*45 + (sy-qy)*3;
                    for (int qx = qxl; qx <= qxh; qx++)
                        acc += Gy[qx*45 + (sx-qx)];
                }
            }
            d_gcls[cls*225 + s] = acc;
        }
        __threadfence();
        __syncthreads();
        if (tid == 0) atomicAdd(&d_flags[0], 1);
    } else if (bflat < 49) {
        // ---- Mp worker (needs full parity MLP); block 45 also publishes offs ----
        float* sbw1 = s_small;          // 192
        float* sbb1 = s_small + 192;    // 64
        float* sbb2 = s_small + 256;    // 64
        float* sr2w = s_small + 320;    // 256
        float* sr2b = s_small + 576;    // 4
        float* sow  = s_small + 580;    // 128
        float* sob  = s_small + 708;    // 2
        for (int t = tid; t < 4096; t += 256) tile[SCR_BW2 + t] = bw2[t];
        for (int t = tid; t < 192;  t += 256) sbw1[t] = bw1[t];
        for (int t = tid; t < 64;   t += 256) { sbb1[t] = bb1[t]; sbb2[t] = bb2[t]; }
        for (int t = tid; t < 256;  t += 256) sr2w[t] = r2w[t];
        for (int t = tid; t < 128;  t += 256) sow[t]  = ow[t];
        if (tid < 4) sr2b[tid] = r2b[tid];
        if (tid < 2) sob[tid]  = ob[tid];
        __syncthreads();
        {
            int p = tid >> 6, o = tid & 63;
            float ch = (p & 2) ? 0.25f : -0.25f;
            float cw = (p & 1) ? 0.25f : -0.25f;
            float a = sbw1[o*3+0]*0.5f + sbw1[o*3+1]*ch + sbw1[o*3+2]*cw + sbb1[o];
            e1s[p][o] = a > 0.f ? a : 0.f;
        }
        __syncthreads();
        {
            int p = tid >> 6, o = tid & 63;
            float a = sbb2[o];
            #pragma unroll 8
            for (int i = 0; i < 64; i++) a += tile[SCR_BW2 + o*64+i]*e1s[p][i];
            e2s[p][o] = a > 0.f ? a : 0.f;
        }
        __syncthreads();
        if (tid < 24) {
            int p = tid / 6, u = tid % 6;
            if (u < 2) {
                float a = sob[u];
                for (int i = 0; i < 64; i++) a += sow[u*64+i]*e2s[p][i];
                offs_w[p*2+u] = a;
            } else {
                int e = u - 2;
                float a = sr2b[e];
                for (int i = 0; i < 64; i++) a += sr2w[e*64+i]*e2s[p][i];
                r2s[p][e] = 1.f/(1.f+expf(-a));
            }
        }
        __syncthreads();
        // block 45 publishes offsets EARLY (unblocks 251 consumer blocks)
        if (bflat == 45) {
            if (tid < 8) d_offp[tid] = offs_w[tid];
            __threadfence();
            __syncthreads();
            if (tid == 0) atomicExch(&d_flags[1], 1);
        }
        // Mp for this block's parity
        {
            int p = bflat - 45;
            float r0 = r2s[p][0], r1 = r2s[p][1], r2 = r2s[p][2], r3 = r2s[p][3];
            for (int ij = tid; ij < 961; ij += 256)
                d_Mp[p*961 + ij] = r0*W2[ij] + r1*W2[961+ij]
                                 + r2*W2[2*961+ij] + r3*W2[3*961+ij];
        }
        __threadfence();
        __syncthreads();
        if (tid == 0) atomicAdd(&d_flags[0], 1);
    }
    __syncthreads();   // worker scratch in tile region now dead everywhere

    // ======================= wait for offsets, then bilinear =======================
    if (tid == 0) {
        while (*((volatile int*)&d_flags[1]) == 0) __nanosleep(64);
    }
    __syncthreads();
    if (tid < 8) offs[tid] = ((volatile float*)d_offp)[tid];
    __syncthreads();

    int gx0 = blockIdx.x*32 - 2, gy0 = blockIdx.y*8 - 2;
    for (int t = tid; t < NT; t += 256) {
        int yy = t / 36, xx = t % 36;
        int gy = gy0 + yy, gx = gx0 + xx;
        float* dst = tile + t*DSTR;
        if (gy < 0 || gy >= HO || gx < 0 || gx >= WO) {
            #pragma unroll
            for (int g = 0; g < 8; g++)
                *(float4*)(dst + 4*g) = make_float4(0.f, 0.f, 0.f, 0.f);
        } else {
            int p = ((gy & 1) << 1) | (gx & 1);
            float ix = (gx + 0.5f)*0.5f - 0.5f + offs[p*2+0];
            float iy = (gy + 0.5f)*0.5f - 0.5f + offs[p*2+1];
            float x0f = floorf(ix), y0f = floorf(iy);
            float wx1 = ix - x0f, wy1 = iy - y0f;
            int x0 = (int)x0f, y0 = (int)y0f;
            float vx0 = (x0   >= 0 && x0   <= WI-1) ? 1.f : 0.f;
            float vx1 = (x0+1 >= 0 && x0+1 <= WI-1) ? 1.f : 0.f;
            float vy0 = (y0   >= 0 && y0   <= HI-1) ? 1.f : 0.f;
            float vy1 = (y0+1 >= 0 && y0+1 <= HI-1) ? 1.f : 0.f;
            int xi0 = min(max(x0,   0), WI-1), xi1 = min(max(x0+1, 0), WI-1);
            int yi0 = min(max(y0,   0), HI-1), yi1 = min(max(y0+1, 0), HI-1);
            float w00 = (1.f-wy1)*(1.f-wx1)*vy0*vx0;
            float w01 = (1.f-wy1)*wx1*vy0*vx1;
            float w10 = wy1*(1.f-wx1)*vy1*vx0;
            float w11 = wy1*wx1*vy1*vx1;
            int b00 = yi0*WI + xi0, b01 = yi0*WI + xi1;
            int b10 = yi1*WI + xi0, b11 = yi1*WI + xi1;
            #pragma unroll 2
            for (int g = 0; g < 8; g++) {
                float4 buf;
                float v0, v1, v2, v3;
                {
                    const float* xc = x + (4*g+0)*(HI*WI);
                    v0 = w00*__ldg(xc+b00) + w01*__ldg(xc+b01)
                       + w10*__ldg(xc+b10) + w11*__ldg(xc+b11);
                }
                {
                    const float* xc = x + (4*g+1)*(HI*WI);
                    v1 = w00*__ldg(xc+b00) + w01*__ldg(xc+b01)
                       + w10*__ldg(xc+b10) + w11*__ldg(xc+b11);
                }
                {
                    const float* xc = x + (4*g+2)*(HI*WI);
                    v2 = w00*__ldg(xc+b00) + w01*__ldg(xc+b01)
                       + w10*__ldg(xc+b10) + w11*__ldg(xc+b11);
                }
                if (g < 7) {
                    const float* xc = x + (4*g+3)*(HI*WI);
                    v3 = w00*__ldg(xc+b00) + w01*__ldg(xc+b01)
                       + w10*__ldg(xc+b10) + w11*__ldg(xc+b11);
                } else {
                    v3 = 0.f;   // depth 31 pad
                }
                buf.x = v0; buf.y = v1; buf.z = v2; buf.w = v3;
                *(float4*)(dst + 4*g) = buf;
            }
        }
    }

    // ======================= wait for tables, stage wcls/Mps =======================
    if (tid == 0) {
        while (*((volatile int*)&d_flags[0]) < 49) __nanosleep(64);
    }
    __syncthreads();

    int oylo = blockIdx.y*8, oxlo = blockIdx.x*32;
    int yec = (oylo == 0) ? 1 : ((oylo + 7 >= HO-1) ? 2 : 0);
    int xec = (oxlo == 0) ? 1 : ((oxlo + 31 >= WO-1) ? 2 : 0);
    int slot_mask = 1 | ((yec ? 1 : 0) << 1) | ((xec ? 1 : 0) << 2)
                  | (((yec && xec) ? 1 : 0) << 3);
    #pragma unroll 1
    for (int slot = 0; slot < 4; slot++) {
        if (!((slot_mask >> slot) & 1)) continue;
        int ys = (slot & 1) ? yec : 0;
        int xs = (slot & 2) ? xec : 0;
        for (int r = tid; r < 1125; r += 256) {
            int zc = r / 225;
            wcls[slot*1125 + r] = d_gcls[((zc*3 + ys)*3 + xs)*225 + (r % 225)];
        }
    }
    for (int t = tid; t < MPS_F; t += 256) {
        int p = t / (31*MROW), r = t % (31*MROW);
        int ii = r / MROW, jj = r % MROW;
        Mps[t] = (jj < 31) ? d_Mp[p*961 + ii*31 + jj] : 0.f;
    }
    __syncthreads();

    // ======================= conv (R11 merged packed) + mix =======================
    int oy = blockIdx.y*8 + ty, ox = blockIdx.x*32 + tx;
    int yfl = (oy == 0 || oy == HO-1) ? 1 : 0;
    int xfl = (ox == 0 || ox == WO-1) ? 1 : 0;
    const float* gY = wcls + (yfl + 2*xfl)*1125;
    const float* ctr = tile + ((ty+2)*36 + (tx+2))*DSTR;

    ull accE[16], accO[15];
    float acc0x = 0.f;
    #pragma unroll
    for (int k = 0; k < 16; k++) accE[k] = *(const ull*)(ctr + 2*k);   // residual init
    #pragma unroll
    for (int k = 0; k < 15; k++) accO[k] = 0ULL;

    #pragma unroll 1
    for (int sy = 0; sy < 5; sy++) {
        #pragma unroll 1
        for (int sx = 0; sx < 5; sx++) {
            const float* tp = tile + ((ty+sy)*36 + (tx+sx))*DSTR;
            const float* gt = gY + sy*5 + sx;   // + zc*225 + sz*25
            ulonglong2 vq[8];
            #pragma unroll
            for (int m = 0; m < 8; m++) vq[m] = *(const ulonglong2*)(tp + 4*m);

            // ---- even sz (accE: pairs (2k,2k+1)) ----
            #pragma unroll
            for (int szh = 0; szh < 5; szh++) {
                const int sz = 2*szh;
                float gi = gt[450 + sz*25];
                ull wII = pk2(gi, gi);
                if (szh >= 2) {
                    fma2(accE[0], VE(szh), pk2(gt[sz*25], gt[225 + sz*25]));
                }
                #pragma unroll
                for (int k = 1; k <= 13; k++) {
                    if (!(k == 1 && szh == 0))
                        fma2(accE[k], VE(k+szh), wII);
                }
                if (szh <= 2) {
                    fma2(accE[14], VE(14+szh), pk2(gi, gt[675 + sz*25]));
                } else if (szh == 3) {
                    fma2(accE[14], VE(17), pk2(gi, 0.f));
                }
                if (szh <= 2) {
                    fma2(accE[15], VE(15+szh), pk2(gt[900 + sz*25], 0.f));
                }
            }
            // ---- odd sz (accO: pairs (2k+1,2k+2)) ----
            #pragma unroll
            for (int szh = 0; szh < 4; szh++) {
                const int sz = 2*szh + 1;
                const int h = szh + 1;
                float gi = gt[450 + sz*25];
                ull wII = pk2(gi, gi);
                if (sz >= 3) {
                    fma2(accO[0], VE(h), pk2(gt[225 + sz*25], gi));
                }
                #pragma unroll
                for (int k = 1; k <= 13; k++)
                    fma2(accO[k], VE(k+h), wII);
                if (sz <= 3) {
                    fma2(accO[14], VE(14+h), pk2(gt[675 + sz*25], gt[900 + sz*25]));
                } else if (sz == 5) {
                    fma2(accO[14], VE(17), pk2(gt[675 + sz*25], 0.f));
                }
                if (sz >= 5) {
                    acc0x += gt[sz*25] * upk(VE(szh)).y;
                }
            }
        }
    }

    float a[32];
    #pragma unroll
    for (int k = 0; k < 16; k++) { float2 e = upk(accE[k]); a[2*k] = e.x; a[2*k+1] = e.y; }
    #pragma unroll
    for (int k = 0; k < 15; k++) { float2 o = upk(accO[k]); a[2*k+1] += o.x; a[2*k+2] += o.y; }
    a[0] += acc0x;
    a[31] = 0.f;

    const float* M = Mps + (((oy & 1) << 1) | (ox & 1))*(31*MROW);
    int pix = oy*WO + ox;
    #pragma unroll 1
    for (int ii = 0; ii < 30; ii += 2) {
        const float* M0 = M + ii*MROW;
        const float* M1 = M0 + MROW;
        float s00 = 0.f, s01 = 0.f, s10 = 0.f, s11 = 0.f;
        #pragma unroll
        for (int jc = 0; jc < 8; jc += 2) {
            float4 a0 = *(const float4*)(M0 + jc*4);
            float4 b0 = *(const float4*)(M0 + jc*4 + 4);
            float4 a1 = *(const float4*)(M1 + jc*4);
            float4 b1 = *(const float4*)(M1 + jc*4 + 4);
            int j0 = jc*4;
            s00 += a0.x*a[j0+0] + a0.y*a[j0+1] + a0.z*a[j0+2] + a0.w*a[j0+3];
            s01 += b0.x*a[j0+4] + b0.y*a[j0+5] + b0.z*a[j0+6] + b0.w*a[j0+7];
            s10 += a1.x*a[j0+0] + a1.y*a[j0+1] + a1.z*a[j0+2] + a1.w*a[j0+3];
            s11 += b1.x*a[j0+4] + b1.y*a[j0+5] + b1.z*a[j0+6] + b1.w*a[j0+7];
        }
        out[ii*NPIX + pix]     = ctr[ii]   + (s00 + s01);
        out[(ii+1)*NPIX + pix] = ctr[ii+1] + (s10 + s11);
    }
    {
        const float* M0 = M + 30*MROW;
        float s0 = 0.f, s1 = 0.f;
        #pragma unroll
        for (int jc = 0; jc < 8; jc += 2) {
            float4 a0 = *(const float4*)(M0 + jc*4);
            float4 b0 = *(const float4*)(M0 + jc*4 + 4);
            int j0 = jc*4;
            s0 += a0.x*a[j0+0] + a0.y*a[j0+1] + a0.z*a[j0+2] + a0.w*a[j0+3];
            s1 += b0.x*a[j0+4] + b0.y*a[j0+5] + b0.z*a[j0+6] + b0.w*a[j0+7];
        }
        out[30*NPIX + pix] = ctr[30] + (s0 + s1);
    }
}

// ============================ launch ============================
extern "C" void kernel_launch(void* const* d_in, const int* in_sizes, int n_in,
                              void* d_out, int out_size)
{
    const float* x   = (const float*)d_in[0];
    // d_in[1] = scale (always 2; parity tables assume it)
    const float* WE  = (const float*)d_in[2];
    const float* WC  = (const float*)d_in[3];
    const float* W2  = (const float*)d_in[4];
    const float* bw1 = (const float*)d_in[5];
    const float* bb1 = (const float*)d_in[6];
    const float* bw2 = (const float*)d_in[7];
    const float* bb2 = (const float*)d_in[8];
    const float* r2w = (const float*)d_in[9];
    const float* r2b = (const float*)d_in[10];
    const float* ow  = (const float*)d_in[11];
    const float* ob  = (const float*)d_in[12];
    const float* l1w = (const float*)d_in[13];
    const float* l1b = (const float*)d_in[14];
    const float* l2w = (const float*)d_in[15];
    const float* l2b = (const float*)d_in[16];
    float* out = (float*)d_out;

    static void* flags_addr = nullptr;
    if (!flags_addr) {
        cudaGetSymbolAddress(&flags_addr, d_flags);
        cudaFuncSetAttribute(kall, cudaFuncAttributeMaxDynamicSharedMemorySize,
                             SMEM_F * (int)sizeof(float));
    }

    cudaMemsetAsync(flags_addr, 0, 2*sizeof(int));
    kall<<<dim3(WO/32, HO/8), dim3(32, 8), SMEM_F*(int)sizeof(float)>>>(
        x, WE, WC, W2, bw1, bb1, bw2, bb2,
        r2w, r2b, ow, ob, l1w, l1b, l2w, l2b, out);
}